// round 13
// baseline (speedup 1.0000x reference)
#include <cuda_runtime.h>
#include <cuda_bf16.h>
#include <math.h>
#include <cstdint>

#define NROWS 8192
#define DDIM  64
#define NCLS  17
#define MARGIN 1.1f
#define EPS 1e-8f
#define TILE 128
#define NTILES (NROWS / TILE)     // 64
#define NPREP  NTILES             // 64 prep blocks
#define NGROUPS 544               // main-pass groups (4 tiles each, one A band)
#define NWORKERS 296              // 2 CTAs/SM x 148 SMs, all wave-1 resident
#define ROWB 144                  // padded smem row stride (bytes)
#define BUFB (TILE * ROWB)        // 18432 bytes per tile buffer
#define SMEM_TOTAL (4 * BUFB + 64)
#define XP_ROWS (NROWS + NCLS * TILE)   // class-sorted, per-class 128-padded

// Scratch (no allocs allowed).
__device__ __align__(16) __nv_bfloat16 g_xb[NROWS * DDIM];    // row order
__device__ __align__(16) __nv_bfloat16 g_xp[XP_ROWS * DDIM];  // class-sorted
__device__ int      g_bh[NPREP][NCLS];   // per-block class histograms
__device__ int      g_htot[NCLS];        // class totals      (block 0)
__device__ int      g_coff[NCLS];        // padded class starts (rows)
__device__ int      g_Tc[NCLS];          // tiles per class side
__device__ double   g_accum;             // zero-init; last block resets
__device__ unsigned g_ctrA, g_ctrB, g_done, g_work;   // reset each run

__device__ __forceinline__ uint32_t smem_u32(const void* p) {
    uint32_t a;
    asm("{ .reg .u64 t; cvta.to.shared.u64 t, %1; cvt.u32.u64 %0, t; }"
        : "=r"(a) : "l"(p));
    return a;
}

__device__ __forceinline__ void ldsm_x4(uint32_t& r0, uint32_t& r1,
                                        uint32_t& r2, uint32_t& r3,
                                        uint32_t addr) {
    asm volatile("ldmatrix.sync.aligned.m8n8.x4.shared.b16 {%0,%1,%2,%3}, [%4];"
                 : "=r"(r0), "=r"(r1), "=r"(r2), "=r"(r3) : "r"(addr));
}

__device__ __forceinline__ void mma_16816(float* c, const uint32_t* a,
                                          uint32_t b0, uint32_t b1) {
    asm volatile(
        "mma.sync.aligned.m16n8k16.row.col.f32.bf16.bf16.f32 "
        "{%0,%1,%2,%3}, {%4,%5,%6,%7}, {%8,%9}, {%0,%1,%2,%3};"
        : "+f"(c[0]), "+f"(c[1]), "+f"(c[2]), "+f"(c[3])
        : "r"(a[0]), "r"(a[1]), "r"(a[2]), "r"(a[3]), "r"(b0), "r"(b1));
}

__device__ __forceinline__ void cpa16(uint32_t dst, const void* src) {
    asm volatile("cp.async.cg.shared.global [%0], [%1], 16;"
                 :: "r"(dst), "l"(src) : "memory");
}
#define CPA_COMMIT() asm volatile("cp.async.commit_group;" ::: "memory")
#define CPA_WAIT(n)  asm volatile("cp.async.wait_group %0;" :: "n"(n) : "memory")

__device__ __forceinline__ void spin_until(unsigned* ctr, unsigned target) {
    unsigned v;
    do {
        asm volatile("ld.acquire.gpu.u32 %0, [%1];" : "=r"(v) : "l"(ctr));
        if (v < target) __nanosleep(64);
    } while (v < target);
}

// ---------------------------------------------------------------------------
// Persistent fused kernel.
//   Prep (blocks 0..63): normalize -> bf16 into g_xb (row order) AND a smem
//   stage; ballot-rank rows by class; after barrier A (histograms), scatter
//   into g_xp class-sorted with per-class zero padding to 128; barrier B.
//   Main pass (units 0..543): Gram tiles over g_xb, epilogue = pure hinge
//   sum h(v)=max(v+MC,0) -- NO class data (3 instr/value).
//   Correction pass (units 544..): within-class padded blocks from g_xp,
//   accumulate -(u+h) per pair, u=v+MC.
//   Finalize: loss*N^2 = acc + 2*MC*P + (1-MC)*R, R=sum h_c^2, P=sum m_c^2.
// ---------------------------------------------------------------------------
__global__ __launch_bounds__(256, 2) void fused_kernel(
    const float* __restrict__ x, const int* __restrict__ cls,
    float* __restrict__ out) {

    extern __shared__ __align__(16) char dsm[];
    char*  sA    = dsm;
    char*  sB    = dsm + BUFB;                    // 3 buffers of BUFB
    float* red   = (float*)(dsm + 4 * BUFB);
    int*   sunit = (int*)(red + 8);

    const int bid  = blockIdx.x;
    const int tid  = threadIdx.x;
    const int wid  = tid >> 5;
    const int lane = tid & 31;
    const float MC = MARGIN - 1.0f;               // exactly representable

    // ================= Phase 1: prep (blocks 0..63) =========================
    if (bid < NPREP) {
        // smem overlay inside dsm (A/B buffers unused yet)
        __nv_bfloat16* stageb = (__nv_bfloat16*)dsm;          // [128][64]
        int* pint   = (int*)(dsm + TILE * DDIM * 2);          // after 16KB
        int* wcount = pint;          // [4][17]
        int* srank  = pint + 68;     // [128]
        int* sbase  = pint + 196;    // [17] offset of this block within class
        int* stot   = pint + 213;    // [17] class totals
        int* spre   = pint + 230;    // [17] padded class starts

        if (tid < 68) wcount[tid] = 0;
        __syncthreads();

        // --- normalize (2 threads/row) -> g_xb + stage ---
        int t    = bid * 256 + tid;
        int row  = t >> 1;
        int half = t & 1;
        int lrow = tid >> 1;
        const float4* xr = (const float4*)(x + (size_t)row * DDIM + half * 32);
        float4 v[8];
        #pragma unroll
        for (int i = 0; i < 8; i++) v[i] = xr[i];
        float s = 0.0f;
        #pragma unroll
        for (int i = 0; i < 8; i++)
            s += v[i].x * v[i].x + v[i].y * v[i].y +
                 v[i].z * v[i].z + v[i].w * v[i].w;
        s += __shfl_xor_sync(0xffffffffu, s, 1);
        float inv = 1.0f / fmaxf(sqrtf(s), EPS);
        __nv_bfloat16* dst = g_xb + (size_t)row * DDIM + half * 32;
        __nv_bfloat16* stg = stageb + lrow * DDIM + half * 32;
        #pragma unroll
        for (int i = 0; i < 8; i++) {
            __nv_bfloat162 p0 = {__float2bfloat16(v[i].x * inv),
                                 __float2bfloat16(v[i].y * inv)};
            __nv_bfloat162 p1 = {__float2bfloat16(v[i].z * inv),
                                 __float2bfloat16(v[i].w * inv)};
            *(__nv_bfloat162*)(dst + i * 4)     = p0;
            *(__nv_bfloat162*)(dst + i * 4 + 2) = p1;
            *(__nv_bfloat162*)(stg + i * 4)     = p0;
            *(__nv_bfloat162*)(stg + i * 4 + 2) = p1;
        }

        // --- deterministic ballot rank (1 thread per row, warps 0..3) ---
        int myc = 0, rank_w = 0;
        if (tid < TILE) {
            myc = cls[bid * TILE + tid];
            unsigned mask = __match_any_sync(0xffffffffu, myc);
            rank_w = __popc(mask & ((1u << lane) - 1u));
            if (rank_w == 0) wcount[(tid >> 5) * NCLS + myc] = __popc(mask);
        }
        __syncthreads();
        if (tid < TILE) {
            int pre = 0, w = tid >> 5;
            for (int w2 = 0; w2 < w; w2++) pre += wcount[w2 * NCLS + myc];
            srank[tid] = rank_w + pre;
        }
        if (tid < NCLS) {
            int h = 0;
            #pragma unroll
            for (int w2 = 0; w2 < 4; w2++) h += wcount[w2 * NCLS + tid];
            g_bh[bid][tid] = h;
        }
        __syncthreads();
        if (tid == 0) { __threadfence(); atomicAdd(&g_ctrA, 1u); }

        // --- wait for all histograms (barrier A) ---
        if (tid == 0) spin_until(&g_ctrA, NPREP);
        __syncthreads();

        // per-class: offset of this block + class totals
        if (tid < NCLS) {
            int before = 0, total = 0;
            for (int b = 0; b < NPREP; b++) {
                int h = g_bh[b][tid];
                total += h;
                if (b < bid) before += h;
            }
            sbase[tid] = before;
            stot[tid]  = total;
        }
        __syncthreads();
        if (tid == 0) {
            int off = 0;
            for (int c = 0; c < NCLS; c++) {
                spre[c] = off;
                int m = ((stot[c] + TILE - 1) >> 7) << 7;
                if (bid == 0) {
                    g_coff[c] = off;
                    g_Tc[c]   = m >> 7;
                    g_htot[c] = stot[c];
                }
                off += m;
            }
        }
        __syncthreads();

        // --- scatter rows to class-sorted padded layout ---
        if (tid < TILE) {
            int pos = spre[myc] + sbase[myc] + srank[tid];
            const uint4* src4 = (const uint4*)(stageb + tid * DDIM);
            uint4* dst4 = (uint4*)(g_xp + (size_t)pos * DDIM);
            #pragma unroll
            for (int q = 0; q < 8; q++) dst4[q] = src4[q];
        }
        // --- block 0: zero the padding rows (idempotent per run) ---
        if (bid == 0) {
            for (int c = 0; c < NCLS; c++) {
                int h = stot[c];
                int m = ((h + TILE - 1) >> 7) << 7;
                int ps = spre[c];
                for (int r = h + tid; r < m; r += 256) {
                    uint4* z = (uint4*)(g_xp + (size_t)(ps + r) * DDIM);
                    uint4 zz = {0, 0, 0, 0};
                    #pragma unroll
                    for (int q = 0; q < 8; q++) z[q] = zz;
                }
            }
        }
        __syncthreads();
        if (tid == 0) { __threadfence(); atomicAdd(&g_ctrB, 1u); }
        __syncthreads();            // dsm overlay dead before worker reuse
    }

    // ---------------- All blocks: wait for normalize (barrier A) ------------
    if (tid == 0) spin_until(&g_ctrA, NPREP);
    __syncthreads();

    const int wm = wid & 3;
    const int wn = wid >> 2;
    const uint32_t a_base = smem_u32(sA);
    const uint32_t bufu[3] = { smem_u32(sB), smem_u32(sB + BUFB),
                               smem_u32(sB + 2 * BUFB) };
    const uint32_t a_lane_off =
        (uint32_t)((wm * 32 + (lane & 15)) * ROWB + ((lane >> 4) << 4));
    const uint32_t b_lane_off =
        (uint32_t)((wn * 64 + (lane & 7) + ((lane >> 4) << 3)) * ROWB +
                   (((lane >> 3) & 1) << 4));

    float lsum = 0.0f;     // carried across ALL stolen units
    bool haveB = false;

    // ==================== Persistent work-stealing loop =====================
    for (;;) {
        if (tid == 0) *sunit = (int)atomicAdd(&g_work, 1u);
        __syncthreads();
        const int unit = *sunit;

        const __nv_bfloat16* srcArr;
        int aRow, bRow0, nb, dIdx;
        bool isClass;

        if (unit < NGROUPS) {
            // ---- main-pass mapping: groups of 4 tiles on one A band ----
            int rem = unit, bi = 0;
            for (;;) {
                int g = (NTILES - bi + 3) >> 2;
                if (rem < g) break;
                rem -= g; bi++;
            }
            int bj0 = bi + rem * 4;
            nb   = min(4, NTILES - bj0);
            aRow = bi * TILE;
            bRow0 = bj0 * TILE;
            dIdx = (bj0 == bi) ? 0 : -1;
            srcArr = g_xb;
            isClass = false;
        } else {
            // ---- correction-pass mapping: rows of tiles within a class ----
            if (!haveB) {
                if (tid == 0) spin_until(&g_ctrB, NPREP);
                __syncthreads();
                haveB = true;
            }
            int u2 = unit - NGROUPS, c = 0;
            while (c < NCLS) {
                int T = g_Tc[c];
                if (u2 < T) break;
                u2 -= T; c++;
            }
            if (c >= NCLS) break;           // all work done
            aRow  = g_coff[c] + u2 * TILE;
            bRow0 = aRow;
            nb    = g_Tc[c] - u2;
            dIdx  = 0;
            srcArr = g_xp;
            isClass = true;
        }

        // ---- Load A band into smem ----
        {
            const uint4* Ag = (const uint4*)(srcArr + (size_t)aRow * DDIM);
            #pragma unroll
            for (int r = 0; r < 4; r++) {
                int idx = tid + r * 256;
                int row = idx >> 3;
                int ch  = idx & 7;
                *(uint4*)(sA + row * ROWB + ch * 16) = Ag[idx];
            }
        }
        // ---- Prefetch B(0) ----
        {
            const char* src = (const char*)(srcArr + (size_t)bRow0 * DDIM);
            #pragma unroll
            for (int r = 0; r < 4; r++) {
                int idx = tid + r * 256;
                int row = idx >> 3;
                int ch  = idx & 7;
                cpa16(bufu[0] + row * ROWB + ch * 16, src + idx * 16);
            }
        }
        CPA_COMMIT();
        __syncthreads();                 // sA visible

        // ---- A fragments in registers for the whole unit ----
        uint32_t aF[4][2][4];
        #pragma unroll
        for (int k = 0; k < 4; k++)
            #pragma unroll
            for (int m = 0; m < 2; m++)
                ldsm_x4(aF[k][m][0], aF[k][m][1], aF[k][m][2], aF[k][m][3],
                        a_base + a_lane_off + m * 16 * ROWB + k * 32);

        for (int t = 0; t < nb; t++) {
            if (t + 1 < nb) {
                const char* src = (const char*)
                    (srcArr + (size_t)(bRow0 + (t + 1) * TILE) * DDIM);
                uint32_t dstp = bufu[(t + 1) % 3];
                #pragma unroll
                for (int r = 0; r < 4; r++) {
                    int idx = tid + r * 256;
                    int row = idx >> 3;
                    int ch  = idx & 7;
                    cpa16(dstp + row * ROWB + ch * 16, src + idx * 16);
                }
                CPA_COMMIT();
                CPA_WAIT(1);
            } else {
                CPA_WAIT(0);
            }
            __syncthreads();

            const uint32_t b_base = bufu[t % 3];

            float c[2][8][4];
            #pragma unroll
            for (int m = 0; m < 2; m++)
                #pragma unroll
                for (int n = 0; n < 8; n++)
                    #pragma unroll
                    for (int e = 0; e < 4; e++) c[m][n][e] = 0.0f;

            #pragma unroll
            for (int k = 0; k < 4; k++) {
                uint32_t b[8][2];
                #pragma unroll
                for (int q = 0; q < 4; q++) {
                    uint32_t r0, r1, r2, r3;
                    ldsm_x4(r0, r1, r2, r3,
                            b_base + b_lane_off + q * 16 * ROWB + k * 32);
                    b[q * 2 + 0][0] = r0; b[q * 2 + 0][1] = r1;
                    b[q * 2 + 1][0] = r2; b[q * 2 + 1][1] = r3;
                }
                #pragma unroll
                for (int m = 0; m < 2; m++)
                    #pragma unroll
                    for (int n = 0; n < 8; n++)
                        mma_16816(c[m][n], aF[k][m], b[n][0], b[n][1]);
            }

            float tl;
            if (!isClass) {
                // ---- main epilogue: pure hinge, no class data ----
                float l0 = 0.0f, l1 = 0.0f, l2 = 0.0f, l3 = 0.0f;
                #pragma unroll
                for (int m = 0; m < 2; m++)
                    #pragma unroll
                    for (int n = 0; n < 8; n++) {
                        l0 += fmaxf(c[m][n][0] + MC, 0.0f);
                        l1 += fmaxf(c[m][n][1] + MC, 0.0f);
                        l2 += fmaxf(c[m][n][2] + MC, 0.0f);
                        l3 += fmaxf(c[m][n][3] + MC, 0.0f);
                    }
                tl = (l0 + l1) + (l2 + l3);
            } else {
                // ---- correction epilogue: accumulate -(u + h) ----
                float l0 = 0.0f, l1 = 0.0f, l2 = 0.0f, l3 = 0.0f;
                #pragma unroll
                for (int m = 0; m < 2; m++)
                    #pragma unroll
                    for (int n = 0; n < 8; n++) {
                        float u0 = c[m][n][0] + MC, u1 = c[m][n][1] + MC;
                        float u2 = c[m][n][2] + MC, u3 = c[m][n][3] + MC;
                        l0 += u0 + fmaxf(u0, 0.0f);
                        l1 += u1 + fmaxf(u1, 0.0f);
                        l2 += u2 + fmaxf(u2, 0.0f);
                        l3 += u3 + fmaxf(u3, 0.0f);
                    }
                tl = -((l0 + l1) + (l2 + l3));
            }
            lsum += (t == dIdx) ? tl : 2.0f * tl;
        }
        __syncthreads();   // all warps done with sA before next unit
    }

    // ---------------- One reduce + atomic per block --------------------------
    #pragma unroll
    for (int o = 16; o; o >>= 1) lsum += __shfl_xor_sync(0xffffffffu, lsum, o);
    if (lane == 0) red[wid] = lsum;
    __syncthreads();
    if (tid == 0) {
        float tt = 0.0f;
        #pragma unroll
        for (int w = 0; w < 8; w++) tt += red[w];
        atomicAdd(&g_accum, (double)tt);
        __threadfence();
        unsigned old = atomicAdd(&g_done, 1u);
        if (old == (unsigned)(NWORKERS - 1)) {
            double R = 0.0, P = 0.0;
            for (int cc = 0; cc < NCLS; cc++) {
                double h = (double)g_htot[cc];
                double m = (double)((((g_htot[cc] + TILE - 1) >> 7)) << 7);
                R += h * h;
                P += m * m;
            }
            const double MCd = (double)(MARGIN - 1.0f);
            double acc = atomicAdd(&g_accum, 0.0);
            double nn  = (double)NROWS * (double)NROWS;
            double total = acc + 2.0 * MCd * P + (1.0 - MCd) * R;
            out[0] = (float)(total / nn);
            g_accum = 0.0;
            g_ctrA  = 0u;
            g_ctrB  = 0u;
            g_done  = 0u;
            g_work  = 0u;
        }
    }
}

extern "C" void kernel_launch(void* const* d_in, const int* in_sizes, int n_in,
                              void* d_out, int out_size) {
    const float* bottleneck = (const float*)d_in[0];
    const int*   class_map  = (const int*)d_in[1];
    float*       out        = (float*)d_out;

    cudaFuncSetAttribute(fused_kernel,
                         cudaFuncAttributeMaxDynamicSharedMemorySize,
                         SMEM_TOTAL);
    fused_kernel<<<NWORKERS, 256, SMEM_TOTAL>>>(bottleneck, class_map, out);
}

// round 14
// speedup vs baseline: 1.1644x; 1.1644x over previous
#include <cuda_runtime.h>
#include <cuda_bf16.h>
#include <math.h>
#include <cstdint>

#define NROWS 8192
#define DDIM  64
#define MARGIN 1.1f
#define EPS 1e-8f
#define TILE 128
#define NTILES 64                 // 64 bands
#define NPREP  64                 // prep blocks
#define NWORKERS 296              // 2 CTAs/SM x 148 SMs
#define NUNITS 600                // 296x5 + 296x2 + 8x1 = 2080 tiles
#define ROWB 144                  // padded smem row stride (bytes)
#define BUFB (TILE * ROWB)        // 18432 B
// dsm: A0 | A1 | B0 | B1 | red[8] | sunit
#define SMEM_TOTAL (4 * BUFB + 64)

// Scratch (no allocs allowed).
__device__ __align__(16) __nv_bfloat16 g_xb[NROWS * DDIM];
__device__ double   g_accum;          // zero-init; last block resets
__device__ unsigned g_prep_done;      // idem
__device__ unsigned g_done_ctr;       // idem
__device__ unsigned g_work;           // work cursor (reset each run)

__device__ __forceinline__ uint32_t smem_u32(const void* p) {
    uint32_t a;
    asm("{ .reg .u64 t; cvta.to.shared.u64 t, %1; cvt.u32.u64 %0, t; }"
        : "=r"(a) : "l"(p));
    return a;
}

__device__ __forceinline__ void ldsm_x4(uint32_t& r0, uint32_t& r1,
                                        uint32_t& r2, uint32_t& r3,
                                        uint32_t addr) {
    asm volatile("ldmatrix.sync.aligned.m8n8.x4.shared.b16 {%0,%1,%2,%3}, [%4];"
                 : "=r"(r0), "=r"(r1), "=r"(r2), "=r"(r3) : "r"(addr));
}

__device__ __forceinline__ void mma_16816(float* c, const uint32_t* a,
                                          uint32_t b0, uint32_t b1) {
    asm volatile(
        "mma.sync.aligned.m16n8k16.row.col.f32.bf16.bf16.f32 "
        "{%0,%1,%2,%3}, {%4,%5,%6,%7}, {%8,%9}, {%0,%1,%2,%3};"
        : "+f"(c[0]), "+f"(c[1]), "+f"(c[2]), "+f"(c[3])
        : "r"(a[0]), "r"(a[1]), "r"(a[2]), "r"(a[3]), "r"(b0), "r"(b1));
}

__device__ __forceinline__ void cpa16(uint32_t dst, const void* src) {
    asm volatile("cp.async.cg.shared.global [%0], [%1], 16;"
                 :: "r"(dst), "l"(src) : "memory");
}
#define CPA_COMMIT() asm volatile("cp.async.commit_group;" ::: "memory")
#define CPA_WAIT0()  asm volatile("cp.async.wait_group 0;" ::: "memory")

// Stage one 128x128B tile (g_xb band) into smem via cp.async.
__device__ __forceinline__ void stage_tile(uint32_t dstb,
                                           const __nv_bfloat16* src, int tid) {
    const char* s = (const char*)src;
    #pragma unroll
    for (int r = 0; r < 4; r++) {
        int idx = tid + r * 256;
        int row = idx >> 3;
        int ch  = idx & 7;
        cpa16(dstb + row * ROWB + ch * 16, s + idx * 16);
    }
}

// Linear triangular tile id -> (bi, bj), bi <= bj.
__device__ __forceinline__ void tile_decode(int t, int& bi, int& bj) {
    int b = (int)((129.0f - sqrtf(16641.0f - 8.0f * (float)t)) * 0.5f);
    while (b * (129 - b) / 2 > t) b--;
    while ((b + 1) * (128 - b) / 2 <= t) b++;
    bi = b;
    bj = b + (t - b * (129 - b) / 2);
}

// ---------------------------------------------------------------------------
// Persistent fused kernel with GUIDED scheduling: unit sizes 5 -> 2 -> 1
// tiles over a linear triangular enumeration (2080 tiles), so every worker
// lands within ~1 tile of the 7.03-tile average (R8's 4-tile units left 48
// workers idle for half the main phase). A is double-buffered and re-staged
// only when bi changes; classes are read directly from gmem (L1-resident).
// ---------------------------------------------------------------------------
__global__ __launch_bounds__(256, 2) void fused_kernel(
    const float* __restrict__ x, const int* __restrict__ cls,
    float* __restrict__ out) {

    extern __shared__ __align__(16) char dsm[];
    float* red   = (float*)(dsm + 4 * BUFB);
    int*   sunit = (int*)(red + 8);

    const int bid  = blockIdx.x;
    const int tid  = threadIdx.x;
    const int wid  = tid >> 5;
    const int lane = tid & 31;

    // ---------------- Phase 1: prep (normalize -> bf16), blocks 0..63 ------
    if (bid < NPREP) {
        int t    = bid * 256 + tid;
        int row  = t >> 1;
        int half = t & 1;
        const float4* xr = (const float4*)(x + (size_t)row * DDIM + half * 32);
        float4 v[8];
        #pragma unroll
        for (int i = 0; i < 8; i++) v[i] = xr[i];
        float s = 0.0f;
        #pragma unroll
        for (int i = 0; i < 8; i++)
            s += v[i].x * v[i].x + v[i].y * v[i].y +
                 v[i].z * v[i].z + v[i].w * v[i].w;
        s += __shfl_xor_sync(0xffffffffu, s, 1);
        float inv = 1.0f / fmaxf(sqrtf(s), EPS);
        __nv_bfloat16* dst = g_xb + (size_t)row * DDIM + half * 32;
        #pragma unroll
        for (int i = 0; i < 8; i++) {
            __nv_bfloat162 p0 = {__float2bfloat16(v[i].x * inv),
                                 __float2bfloat16(v[i].y * inv)};
            __nv_bfloat162 p1 = {__float2bfloat16(v[i].z * inv),
                                 __float2bfloat16(v[i].w * inv)};
            *(__nv_bfloat162*)(dst + i * 4)     = p0;
            *(__nv_bfloat162*)(dst + i * 4 + 2) = p1;
        }
        __syncthreads();
        if (tid == 0) { __threadfence(); atomicAdd(&g_prep_done, 1u); }
    }

    // ---------------- Device-wide wait for prep ----------------------------
    if (tid == 0) {
        unsigned v;
        do {
            asm volatile("ld.acquire.gpu.u32 %0, [%1];"
                         : "=r"(v) : "l"(&g_prep_done));
            if (v < (unsigned)NPREP) __nanosleep(64);
        } while (v < (unsigned)NPREP);
    }
    __syncthreads();

    const int wm = wid & 3;
    const int wn = wid >> 2;
    const uint32_t aBufu[2] = { smem_u32(dsm), smem_u32(dsm + BUFB) };
    const uint32_t bBufu[2] = { smem_u32(dsm + 2 * BUFB),
                                smem_u32(dsm + 3 * BUFB) };
    const uint32_t a_lane_off =
        (uint32_t)((wm * 32 + (lane & 15)) * ROWB + ((lane >> 4) << 4));
    const uint32_t b_lane_off =
        (uint32_t)((wn * 64 + (lane & 7) + ((lane >> 4) << 3)) * ROWB +
                   (((lane >> 3) & 1) << 4));
    const float MC = MARGIN - 1.0f;
    const int quad = lane >> 2;
    const int tq   = lane & 3;

    int curAbi = -1;      // bi resident in aBufu[aCur] (after wait)
    int aCur   = 0;
    int aFbi   = -1;      // bi currently in aF registers
    int wcnt   = 0;       // tiles processed by this worker (B buffer parity)
    uint32_t aF[4][2][4];
    int ci00 = 0, ci01 = 0, ci10 = 0, ci11 = 0;
    float lsum = 0.0f;

    // ==================== Persistent guided-stealing loop ===================
    for (;;) {
        if (tid == 0) *sunit = (int)atomicAdd(&g_work, 1u);
        __syncthreads();             // also fences prev unit's smem reads
        const int u = *sunit;
        if (u >= NUNITS) break;

        int s, n;
        if (u < 296)      { s = u * 5;                 n = 5; }
        else if (u < 592) { s = 1480 + (u - 296) * 2;  n = 2; }
        else              { s = 2072 + (u - 592);      n = 1; }

        int cbi, cbj;
        tile_decode(s, cbi, cbj);
        if (cbi != curAbi)
            stage_tile(aBufu[aCur ^ 1], g_xb + (size_t)cbi * TILE * DDIM, tid);
        stage_tile(bBufu[wcnt & 1], g_xb + (size_t)cbj * TILE * DDIM, tid);
        CPA_COMMIT();

        int nbi = cbi, nbj = cbj;
        for (int i = 0; i < n; i++) {
            cbi = nbi; cbj = nbj;
            CPA_WAIT0();
            __syncthreads();         // tile data ready, all warps past t-1
            if (cbi != curAbi) { aCur ^= 1; curAbi = cbi; }

            // prefetch next tile (A only if band changes)
            if (i + 1 < n) {
                tile_decode(s + i + 1, nbi, nbj);
                if (nbi != curAbi)
                    stage_tile(aBufu[aCur ^ 1],
                               g_xb + (size_t)nbi * TILE * DDIM, tid);
                stage_tile(bBufu[(wcnt + 1) & 1],
                           g_xb + (size_t)nbj * TILE * DDIM, tid);
                CPA_COMMIT();
            }

            // A fragments + row classes: refresh only on band change
            if (aFbi != cbi) {
                const uint32_t ab = aBufu[aCur];
                #pragma unroll
                for (int k = 0; k < 4; k++)
                    #pragma unroll
                    for (int m = 0; m < 2; m++)
                        ldsm_x4(aF[k][m][0], aF[k][m][1],
                                aF[k][m][2], aF[k][m][3],
                                ab + a_lane_off + m * 16 * ROWB + k * 32);
                aFbi = cbi;
                const int* cr = cls + cbi * TILE + wm * 32 + quad;
                ci00 = __ldg(cr);      ci01 = __ldg(cr + 8);
                ci10 = __ldg(cr + 16); ci11 = __ldg(cr + 24);
            }

            const uint32_t b_base = bBufu[wcnt & 1];

            float c[2][8][4];
            #pragma unroll
            for (int m = 0; m < 2; m++)
                #pragma unroll
                for (int nn = 0; nn < 8; nn++)
                    #pragma unroll
                    for (int e = 0; e < 4; e++) c[m][nn][e] = 0.0f;

            #pragma unroll
            for (int k = 0; k < 4; k++) {
                uint32_t b[8][2];
                #pragma unroll
                for (int q = 0; q < 4; q++) {
                    uint32_t r0, r1, r2, r3;
                    ldsm_x4(r0, r1, r2, r3,
                            b_base + b_lane_off + q * 16 * ROWB + k * 32);
                    b[q * 2 + 0][0] = r0; b[q * 2 + 0][1] = r1;
                    b[q * 2 + 1][0] = r2; b[q * 2 + 1][1] = r3;
                }
                #pragma unroll
                for (int m = 0; m < 2; m++)
                    #pragma unroll
                    for (int nn = 0; nn < 8; nn++)
                        mma_16816(c[m][nn], aF[k][m], b[nn][0], b[nn][1]);
            }

            // ---- Hinge epilogue; classes direct from gmem (L1-resident) ----
            const int* cj = cls + cbj * TILE + wn * 64 + tq * 2;
            float l0 = 0.0f, l1 = 0.0f;
            #pragma unroll
            for (int m = 0; m < 2; m++) {
                const int ci0 = m ? ci10 : ci00;
                const int ci1 = m ? ci11 : ci01;
                #pragma unroll
                for (int nn = 0; nn < 8; nn++) {
                    const int2 cjp = __ldg((const int2*)(cj + nn * 8));
                    float v0 = c[m][nn][0], v1 = c[m][nn][1];
                    float v2 = c[m][nn][2], v3 = c[m][nn][3];
                    l0 += (ci0 == cjp.x) ? (1.0f - v0) : fmaxf(v0 + MC, 0.0f);
                    l1 += (ci0 == cjp.y) ? (1.0f - v1) : fmaxf(v1 + MC, 0.0f);
                    l0 += (ci1 == cjp.x) ? (1.0f - v2) : fmaxf(v2 + MC, 0.0f);
                    l1 += (ci1 == cjp.y) ? (1.0f - v3) : fmaxf(v3 + MC, 0.0f);
                }
            }
            float tl = l0 + l1;
            lsum += (cbi == cbj) ? tl : 2.0f * tl;
            wcnt++;
        }
    }

    // ---------------- One reduce + atomic per block --------------------------
    #pragma unroll
    for (int o = 16; o; o >>= 1) lsum += __shfl_xor_sync(0xffffffffu, lsum, o);
    if (lane == 0) red[wid] = lsum;
    __syncthreads();
    if (tid == 0) {
        float tt = 0.0f;
        #pragma unroll
        for (int w = 0; w < 8; w++) tt += red[w];
        atomicAdd(&g_accum, (double)tt);
        __threadfence();
        unsigned old = atomicAdd(&g_done_ctr, 1u);
        if (old == (unsigned)(NWORKERS - 1)) {
            double a = atomicAdd(&g_accum, 0.0);
            out[0] = (float)(a / ((double)NROWS * (double)NROWS));
            g_accum     = 0.0;
            g_done_ctr  = 0u;
            g_prep_done = 0u;
            g_work      = 0u;
        }
    }
}

extern "C" void kernel_launch(void* const* d_in, const int* in_sizes, int n_in,
                              void* d_out, int out_size) {
    const float* bottleneck = (const float*)d_in[0];
    const int*   class_map  = (const int*)d_in[1];
    float*       out        = (float*)d_out;

    cudaFuncSetAttribute(fused_kernel,
                         cudaFuncAttributeMaxDynamicSharedMemorySize,
                         SMEM_TOTAL);
    fused_kernel<<<NWORKERS, 256, SMEM_TOTAL>>>(bottleneck, class_map, out);
}